// round 2
// baseline (speedup 1.0000x reference)
#include <cuda_runtime.h>
#include <cuda_bf16.h>
#include <cstdint>

#define N_NODES 100000
#define N_EDGES 1600000
#define D 128
#define CAP 64
#define OVF_CAP 8192

// ---------------- scratch (static device globals; no runtime allocation) ----
__device__ float g_support[(size_t)N_NODES * D];       // x @ W   (51.2 MB)
__device__ int   g_deg[N_NODES];
__device__ int   g_bsrc[(size_t)N_NODES * CAP];        // bucketed edge srcs
__device__ float g_bval[(size_t)N_NODES * CAP];        // bucketed edge vals
__device__ int   g_ovfn;
__device__ int   g_ovf_src[OVF_CAP];
__device__ int   g_ovf_dst[OVF_CAP];
__device__ float g_ovf_val[OVF_CAP];

// ---------------- 1) zero counters ------------------------------------------
__global__ void zero_kernel() {
    int i = blockIdx.x * blockDim.x + threadIdx.x;
    if (i < N_NODES) g_deg[i] = 0;
    if (i == 0) g_ovfn = 0;
}

// ---------------- 2) bucket edges by destination ----------------------------
__global__ void bucket_kernel(const int* __restrict__ esrc,
                              const int* __restrict__ edst,
                              const float* __restrict__ aval) {
    int e = blockIdx.x * blockDim.x + threadIdx.x;
    if (e >= N_EDGES) return;
    int d = edst[e];
    int s = esrc[e];
    float v = aval[e];
    int p = atomicAdd(&g_deg[d], 1);
    if (p < CAP) {
        g_bsrc[d * CAP + p] = s;
        g_bval[d * CAP + p] = v;
    } else {
        int o = atomicAdd(&g_ovfn, 1);
        if (o < OVF_CAP) {
            g_ovf_src[o] = s;
            g_ovf_dst[o] = d;
            g_ovf_val[o] = v;
        }
    }
}

// ---------------- 3) support = x @ W  (fp32, smem-tiled) --------------------
// Block: 256 threads, 32 rows of x per block. W staged in two 64-row halves
// (32 KB each) so everything fits in 48 KB static smem.
__global__ __launch_bounds__(256, 4)
void gemm_kernel(const float* __restrict__ x,
                 const float* __restrict__ w,
                 float* __restrict__ support) {
    __shared__ float ws[64 * 128];   // 32 KB: half of W
    __shared__ float xs[32 * 128];   // 16 KB: 32 rows of x

    int t   = threadIdx.x;
    int cg  = t & 31;                // column group: cols 4*cg .. 4*cg+3
    int rg  = t >> 5;                // row group: rows rg*4 .. rg*4+3
    int row0 = blockIdx.x * 32;

    float acc[4][4];
    #pragma unroll
    for (int r = 0; r < 4; r++)
        #pragma unroll
        for (int c = 0; c < 4; c++) acc[r][c] = 0.f;

    // load x tile (clamp out-of-range rows to row 0; stores are guarded)
    #pragma unroll
    for (int i = t; i < 32 * 128 / 4; i += 256) {
        int r = i >> 5, c4 = i & 31;
        int gr = row0 + r;
        if (gr >= N_NODES) gr = 0;
        ((float4*)xs)[i] = ((const float4*)(x + (size_t)gr * 128))[c4];
    }

    for (int half = 0; half < 2; half++) {
        __syncthreads();             // protect ws reuse across halves
        #pragma unroll
        for (int i = t; i < 64 * 128 / 4; i += 256)
            ((float4*)ws)[i] = ((const float4*)w)[half * 2048 + i];
        __syncthreads();

        #pragma unroll
        for (int k0 = 0; k0 < 64; k0 += 4) {
            float4 xv[4];
            #pragma unroll
            for (int r = 0; r < 4; r++)
                xv[r] = *(const float4*)&xs[(rg * 4 + r) * 128 + half * 64 + k0];
            #pragma unroll
            for (int kk = 0; kk < 4; kk++) {
                float4 wv = ((const float4*)ws)[(k0 + kk) * 32 + cg];
                #pragma unroll
                for (int r = 0; r < 4; r++) {
                    float xr = (&xv[r].x)[kk];
                    acc[r][0] = fmaf(xr, wv.x, acc[r][0]);
                    acc[r][1] = fmaf(xr, wv.y, acc[r][1]);
                    acc[r][2] = fmaf(xr, wv.z, acc[r][2]);
                    acc[r][3] = fmaf(xr, wv.w, acc[r][3]);
                }
            }
        }
    }

    #pragma unroll
    for (int r = 0; r < 4; r++) {
        int gr = row0 + rg * 4 + r;
        if (gr < N_NODES) {
            float4 v = make_float4(acc[r][0], acc[r][1], acc[r][2], acc[r][3]);
            ((float4*)(support + (size_t)gr * 128))[cg] = v;
        }
    }
}

// ---------------- 4) gather + bias + residual + relu ------------------------
// One warp per destination node. Lane l owns columns 4l..4l+3 (one float4).
__global__ __launch_bounds__(256)
void gather_kernel(const float* __restrict__ y,
                   const float* __restrict__ bias,
                   float* __restrict__ out) {
    int warp = (blockIdx.x * blockDim.x + threadIdx.x) >> 5;
    int lane = threadIdx.x & 31;
    if (warp >= N_NODES) return;
    int node = warp;

    const float4* sup4 = (const float4*)g_support;
    float4 b = ((const float4*)bias)[lane];
    float4 acc = ((const float4*)y)[(size_t)node * 32 + lane];
    acc.x += b.x; acc.y += b.y; acc.z += b.z; acc.w += b.w;

    int dn = g_deg[node];
    int m  = dn < CAP ? dn : CAP;
    int base = node * CAP;

    #pragma unroll 2
    for (int j = 0; j < m; j++) {
        int s   = g_bsrc[base + j];
        float v = g_bval[base + j];
        float4 sp = sup4[(size_t)s * 32 + lane];
        acc.x = fmaf(v, sp.x, acc.x);
        acc.y = fmaf(v, sp.y, acc.y);
        acc.z = fmaf(v, sp.z, acc.z);
        acc.w = fmaf(v, sp.w, acc.w);
    }

    if (dn > CAP) {  // statistically never; correctness safety net
        int oc = g_ovfn;
        if (oc > OVF_CAP) oc = OVF_CAP;
        for (int k = 0; k < oc; k++) {
            if (g_ovf_dst[k] == node) {
                int s   = g_ovf_src[k];
                float v = g_ovf_val[k];
                float4 sp = sup4[(size_t)s * 32 + lane];
                acc.x = fmaf(v, sp.x, acc.x);
                acc.y = fmaf(v, sp.y, acc.y);
                acc.z = fmaf(v, sp.z, acc.z);
                acc.w = fmaf(v, sp.w, acc.w);
            }
        }
    }

    acc.x = fmaxf(acc.x, 0.f);
    acc.y = fmaxf(acc.y, 0.f);
    acc.z = fmaxf(acc.z, 0.f);
    acc.w = fmaxf(acc.w, 0.f);
    ((float4*)out)[(size_t)node * 32 + lane] = acc;
}

// ---------------- launch -----------------------------------------------------
extern "C" void kernel_launch(void* const* d_in, const int* in_sizes, int n_in,
                              void* d_out, int out_size) {
    const float* x    = (const float*)d_in[0];
    const float* y    = (const float*)d_in[1];
    const int*   esrc = (const int*)d_in[2];
    const int*   edst = (const int*)d_in[3];
    const float* aval = (const float*)d_in[4];
    const float* w    = (const float*)d_in[5];
    const float* bias = (const float*)d_in[6];
    float* out = (float*)d_out;

    float* support;
    cudaGetSymbolAddress((void**)&support, g_support);

    zero_kernel<<<(N_NODES + 255) / 256, 256>>>();
    bucket_kernel<<<(N_EDGES + 255) / 256, 256>>>(esrc, edst, aval);
    gemm_kernel<<<(N_NODES + 31) / 32, 256>>>(x, w, support);
    gather_kernel<<<(N_NODES * 32 + 255) / 256, 256>>>(y, bias, out);
}

// round 4
// speedup vs baseline: 1.0824x; 1.0824x over previous
#include <cuda_runtime.h>
#include <cuda_bf16.h>
#include <cstdint>

#define N_NODES 100000
#define N_EDGES 1600000
#define D 128
#define CAP 64
#define OVF_CAP 8192

// ---------------- scratch (static device globals; no runtime allocation) ----
__device__ float g_support[(size_t)N_NODES * D];       // x @ W   (51.2 MB)
__device__ int   g_deg[N_NODES];
__device__ int   g_bsrc[(size_t)N_NODES * CAP];        // bucketed edge srcs
__device__ float g_bval[(size_t)N_NODES * CAP];        // bucketed edge vals
__device__ int   g_ovfn;
__device__ int   g_ovf_src[OVF_CAP];
__device__ int   g_ovf_dst[OVF_CAP];
__device__ float g_ovf_val[OVF_CAP];

__device__ __forceinline__ uint32_t cvt_tf32(float f) {
    uint32_t r;
    asm("cvt.rna.tf32.f32 %0, %1;" : "=r"(r) : "f"(f));
    return r;
}

// mma.sync m16n8k8 tf32: D += A*B (A row-major 16x8, B col-major 8x8)
#define MMA_TF32(d0, d1, d2, d3, a0, a1, a2, a3, b0, b1)                        \
    asm volatile(                                                               \
        "mma.sync.aligned.m16n8k8.row.col.f32.tf32.tf32.f32 "                   \
        "{%0,%1,%2,%3}, {%4,%5,%6,%7}, {%8,%9}, {%0,%1,%2,%3};"                 \
        : "+f"(d0), "+f"(d1), "+f"(d2), "+f"(d3)                                \
        : "r"(a0), "r"(a1), "r"(a2), "r"(a3), "r"(b0), "r"(b1))

// ---------------- 1) zero counters ------------------------------------------
__global__ void zero_kernel() {
    int i = blockIdx.x * blockDim.x + threadIdx.x;
    if (i < N_NODES) g_deg[i] = 0;
    if (i == 0) g_ovfn = 0;
}

// ---------------- 2) bucket edges by destination ----------------------------
__global__ void bucket_kernel(const int* __restrict__ esrc,
                              const int* __restrict__ edst,
                              const float* __restrict__ aval) {
    int e = blockIdx.x * blockDim.x + threadIdx.x;
    if (e >= N_EDGES) return;
    int d = edst[e];
    int s = esrc[e];
    float v = aval[e];
    int p = atomicAdd(&g_deg[d], 1);
    if (p < CAP) {
        g_bsrc[d * CAP + p] = s;
        g_bval[d * CAP + p] = v;
    } else {
        int o = atomicAdd(&g_ovfn, 1);
        if (o < OVF_CAP) {
            g_ovf_src[o] = s;
            g_ovf_dst[o] = d;
            g_ovf_val[o] = v;
        }
    }
}

// ---------------- 3) support = x @ W  via mma.sync tf32 ---------------------
// Block: 512 threads = 16 warps (4x4 warp grid). M-tile 256 rows, N = 128.
// Warp tile: 64 rows x 32 cols -> 4 m-frags x 4 n-frags of m16n8k8, 16 k-steps.
// Smem (dynamic): A 256 x (stride 132) tf32, B 128 x (stride 136) tf32.
// Padding: A bank = (4*row+col)%32 -> conflict-free; B bank = (8*k+n)%32 -> c-f.
#define A_STRIDE 132
#define B_STRIDE 136
#define SM_A_BYTES (256 * A_STRIDE * 4)               // 135168
#define SM_B_BYTES (128 * B_STRIDE * 4)               // 69632
#define SM_GEMM (SM_A_BYTES + SM_B_BYTES)             // 204800
#define M_TILE 256
#define GEMM_BLOCKS ((N_NODES + M_TILE - 1) / M_TILE) // 391

__global__ __launch_bounds__(512, 1)
void gemm_mma_kernel(const float* __restrict__ x,
                     const float* __restrict__ w,
                     float* __restrict__ support) {
    extern __shared__ uint32_t sm[];
    uint32_t* As = sm;                       // [256][A_STRIDE]
    uint32_t* Bs = sm + 256 * A_STRIDE;      // [128][B_STRIDE]

    int tid  = threadIdx.x;
    int wid  = tid >> 5;
    int lane = tid & 31;
    int wr   = wid >> 2;        // warp row 0..3  -> rows wr*64
    int wc   = wid & 3;         // warp col 0..3  -> cols wc*32
    int lr   = lane >> 2;       // 0..7
    int lc   = lane & 3;        // 0..3
    int row0 = blockIdx.x * M_TILE;

    // stage A (x tile), tf32-converted, padded stride
    for (int idx = tid; idx < M_TILE * 32; idx += 512) {
        int r = idx >> 5, c4 = idx & 31;
        int gr = row0 + r;
        if (gr >= N_NODES) gr = N_NODES - 1;
        float4 v = ((const float4*)(x + (size_t)gr * 128))[c4];
        uint4 t;
        t.x = cvt_tf32(v.x); t.y = cvt_tf32(v.y);
        t.z = cvt_tf32(v.z); t.w = cvt_tf32(v.w);
        *(uint4*)&As[r * A_STRIDE + c4 * 4] = t;
    }
    // stage B (W), tf32-converted: Bs[k][n]
    for (int idx = tid; idx < 128 * 32; idx += 512) {
        int k = idx >> 5, c4 = idx & 31;
        float4 v = ((const float4*)w)[k * 32 + c4];
        uint4 t;
        t.x = cvt_tf32(v.x); t.y = cvt_tf32(v.y);
        t.z = cvt_tf32(v.z); t.w = cvt_tf32(v.w);
        *(uint4*)&Bs[k * B_STRIDE + c4 * 4] = t;
    }
    __syncthreads();

    float acc[4][4][4];   // [m-frag][n-frag][c0..c3]
    #pragma unroll
    for (int m = 0; m < 4; m++)
        #pragma unroll
        for (int n = 0; n < 4; n++)
            #pragma unroll
            for (int q = 0; q < 4; q++) acc[m][n][q] = 0.f;

    #pragma unroll 4
    for (int ks = 0; ks < 16; ks++) {
        int k0 = ks * 8;
        uint32_t af[4][4], bf[4][2];
        #pragma unroll
        for (int m = 0; m < 4; m++) {
            int r = wr * 64 + m * 16 + lr;
            af[m][0] = As[r * A_STRIDE + k0 + lc];
            af[m][1] = As[(r + 8) * A_STRIDE + k0 + lc];
            af[m][2] = As[r * A_STRIDE + k0 + lc + 4];
            af[m][3] = As[(r + 8) * A_STRIDE + k0 + lc + 4];
        }
        #pragma unroll
        for (int n = 0; n < 4; n++) {
            int nn = wc * 32 + n * 8 + lr;
            bf[n][0] = Bs[(k0 + lc) * B_STRIDE + nn];
            bf[n][1] = Bs[(k0 + lc + 4) * B_STRIDE + nn];
        }
        #pragma unroll
        for (int m = 0; m < 4; m++)
            #pragma unroll
            for (int n = 0; n < 4; n++)
                MMA_TF32(acc[m][n][0], acc[m][n][1], acc[m][n][2], acc[m][n][3],
                         af[m][0], af[m][1], af[m][2], af[m][3],
                         bf[n][0], bf[n][1]);
    }

    // epilogue: c0,c1 at (row, 2*lc), c2,c3 at (row+8, 2*lc)
    #pragma unroll
    for (int m = 0; m < 4; m++) {
        int r = row0 + wr * 64 + m * 16 + lr;
        #pragma unroll
        for (int n = 0; n < 4; n++) {
            int col = wc * 32 + n * 8 + lc * 2;
            if (r < N_NODES) {
                float2 v0 = make_float2(acc[m][n][0], acc[m][n][1]);
                *(float2*)(support + (size_t)r * 128 + col) = v0;
            }
            if (r + 8 < N_NODES) {
                float2 v1 = make_float2(acc[m][n][2], acc[m][n][3]);
                *(float2*)(support + (size_t)(r + 8) * 128 + col) = v1;
            }
        }
    }
}

// ---------------- 4) gather + bias + residual + relu ------------------------
// One warp per destination node. Lane l owns one float4 (cols 4l..4l+3).
// Indices/values batched 4-wide (16B loads) so 4 gathers are in flight.
__global__ __launch_bounds__(256)
void gather_kernel(const float* __restrict__ y,
                   const float* __restrict__ bias,
                   float* __restrict__ out) {
    int warp = (blockIdx.x * blockDim.x + threadIdx.x) >> 5;
    int lane = threadIdx.x & 31;
    if (warp >= N_NODES) return;
    int node = warp;

    const float4* sup4 = (const float4*)g_support;
    float4 b = ((const float4*)bias)[lane];
    float4 acc = ((const float4*)y)[(size_t)node * 32 + lane];
    acc.x += b.x; acc.y += b.y; acc.z += b.z; acc.w += b.w;

    int dn = g_deg[node];
    int m  = dn < CAP ? dn : CAP;
    int base = node * CAP;

    int j = 0;
    for (; j + 4 <= m; j += 4) {
        int4   s4 = *(const int4*)&g_bsrc[base + j];
        float4 v4 = *(const float4*)&g_bval[base + j];
        float4 a0 = sup4[(size_t)s4.x * 32 + lane];
        float4 a1 = sup4[(size_t)s4.y * 32 + lane];
        float4 a2 = sup4[(size_t)s4.z * 32 + lane];
        float4 a3 = sup4[(size_t)s4.w * 32 + lane];
        acc.x = fmaf(v4.x, a0.x, acc.x); acc.y = fmaf(v4.x, a0.y, acc.y);
        acc.z = fmaf(v4.x, a0.z, acc.z); acc.w = fmaf(v4.x, a0.w, acc.w);
        acc.x = fmaf(v4.y, a1.x, acc.x); acc.y = fmaf(v4.y, a1.y, acc.y);
        acc.z = fmaf(v4.y, a1.z, acc.z); acc.w = fmaf(v4.y, a1.w, acc.w);
        acc.x = fmaf(v4.z, a2.x, acc.x); acc.y = fmaf(v4.z, a2.y, acc.y);
        acc.z = fmaf(v4.z, a2.z, acc.z); acc.w = fmaf(v4.z, a2.w, acc.w);
        acc.x = fmaf(v4.w, a3.x, acc.x); acc.y = fmaf(v4.w, a3.y, acc.y);
        acc.z = fmaf(v4.w, a3.z, acc.z); acc.w = fmaf(v4.w, a3.w, acc.w);
    }
    for (; j < m; j++) {
        int s   = g_bsrc[base + j];
        float v = g_bval[base + j];
        float4 sp = sup4[(size_t)s * 32 + lane];
        acc.x = fmaf(v, sp.x, acc.x);
        acc.y = fmaf(v, sp.y, acc.y);
        acc.z = fmaf(v, sp.z, acc.z);
        acc.w = fmaf(v, sp.w, acc.w);
    }

    if (dn > CAP) {  // statistically never; correctness safety net
        int oc = g_ovfn;
        if (oc > OVF_CAP) oc = OVF_CAP;
        for (int k = 0; k < oc; k++) {
            if (g_ovf_dst[k] == node) {
                int s   = g_ovf_src[k];
                float v = g_ovf_val[k];
                float4 sp = sup4[(size_t)s * 32 + lane];
                acc.x = fmaf(v, sp.x, acc.x);
                acc.y = fmaf(v, sp.y, acc.y);
                acc.z = fmaf(v, sp.z, acc.z);
                acc.w = fmaf(v, sp.w, acc.w);
            }
        }
    }

    acc.x = fmaxf(acc.x, 0.f);
    acc.y = fmaxf(acc.y, 0.f);
    acc.z = fmaxf(acc.z, 0.f);
    acc.w = fmaxf(acc.w, 0.f);
    ((float4*)out)[(size_t)node * 32 + lane] = acc;
}

// ---------------- launch -----------------------------------------------------
extern "C" void kernel_launch(void* const* d_in, const int* in_sizes, int n_in,
                              void* d_out, int out_size) {
    const float* x    = (const float*)d_in[0];
    const float* y    = (const float*)d_in[1];
    const int*   esrc = (const int*)d_in[2];
    const int*   edst = (const int*)d_in[3];
    const float* aval = (const float*)d_in[4];
    const float* w    = (const float*)d_in[5];
    const float* bias = (const float*)d_in[6];
    float* out = (float*)d_out;

    float* support;
    cudaGetSymbolAddress((void**)&support, g_support);

    cudaFuncSetAttribute(gemm_mma_kernel,
                         cudaFuncAttributeMaxDynamicSharedMemorySize, SM_GEMM);

    zero_kernel<<<(N_NODES + 255) / 256, 256>>>();
    bucket_kernel<<<(N_EDGES + 255) / 256, 256>>>(esrc, edst, aval);
    gemm_mma_kernel<<<GEMM_BLOCKS, 512, SM_GEMM>>>(x, w, support);
    gather_kernel<<<(N_NODES * 32 + 255) / 256, 256>>>(y, bias, out);
}